// round 4
// baseline (speedup 1.0000x reference)
#include <cuda_runtime.h>
#include <cuda_bf16.h>

// Problem dims
#define U_LEN 2048
#define R_LEN 256
#define L_LEN 1024
#define M_LEN 512
#define D_DIM 1024
#define NHEAD 16
#define HDIM  64
#define QLEN  (U_LEN + R_LEN)                   // 2304
#define KVLEN (M_LEN + R_LEN + L_LEN + U_LEN)   // 3840
#define MR    (M_LEN + R_LEN)                   // 768

typedef unsigned long long ull;

// Scratch (no cudaMalloc allowed)
__device__ float g_query[QLEN * D_DIM];
__device__ float g_attn [QLEN * D_DIM];

// ---------------------------------------------------------------------------
// helpers
// ---------------------------------------------------------------------------
__device__ __forceinline__ unsigned f2tf32(float f) {
    unsigned r;
    asm("cvt.rna.tf32.f32 %0, %1;" : "=r"(r) : "f"(f));
    return r;
}

__device__ __forceinline__ void mma_tf32(float* d, const unsigned* a, unsigned b0, unsigned b1) {
    asm volatile(
        "mma.sync.aligned.m16n8k8.row.col.f32.tf32.tf32.f32 "
        "{%0,%1,%2,%3}, {%4,%5,%6,%7}, {%8,%9}, {%0,%1,%2,%3};"
        : "+f"(d[0]), "+f"(d[1]), "+f"(d[2]), "+f"(d[3])
        : "r"(a[0]), "r"(a[1]), "r"(a[2]), "r"(a[3]), "r"(b0), "r"(b1));
}

__device__ __forceinline__ void cp16(void* s, const void* g) {
    unsigned sa = (unsigned)__cvta_generic_to_shared(s);
    asm volatile("cp.async.cg.shared.global [%0], [%1], 16;" :: "r"(sa), "l"(g));
}
#define CP_COMMIT() asm volatile("cp.async.commit_group;")
#define CP_WAIT0()  asm volatile("cp.async.wait_group 0;" ::: "memory")

// ---------------------------------------------------------------------------
// TF32 tensor-core GEMM: C[M,N] = gather(A)[M,K] @ W[N,K]^T + bias
// BM=128, BN=128, BK=16; 256 threads (8 warps: 4 rows x 2 cols), warp = 32x64.
// MODE 0: A = concat(right, utter)        -> g_query
// MODE 1: A = concat(mem, right, utter)   -> scatter to key/value (N=2048)
// MODE 2: A = g_attn                      -> out
// ---------------------------------------------------------------------------
template <int MODE>
__global__ __launch_bounds__(256)
void gemm_tf32(const float* __restrict__ A0,
               const float* __restrict__ A1,
               const float* __restrict__ A2,
               const float* __restrict__ W,
               const float* __restrict__ bias,
               float* __restrict__ C0,
               float* __restrict__ C1)
{
    __shared__ unsigned As[128][20];
    __shared__ unsigned Bs[128][20];

    const int tid  = threadIdx.x;
    const int lane = tid & 31;
    const int warp = tid >> 5;
    const int wr   = warp & 3;          // warp row (0..3) -> m offset wr*32
    const int wc   = warp >> 2;         // warp col (0..1) -> n offset wc*64
    const int bm = blockIdx.y, bn = blockIdx.x;
    const int K = D_DIM, KT = K / 16;
    const int tig = lane & 3, grp = lane >> 2;

    // A rows for this thread (2 float4 loads: row = tid/4 + 64*i, col4 = tid&3)
    const float* arow[2];
#pragma unroll
    for (int i = 0; i < 2; i++) {
        int row = bm * 128 + (tid >> 2) + 64 * i;
        if (MODE == 0) {
            arow[i] = (row < R_LEN) ? (A1 + (size_t)row * D_DIM)
                                    : (A0 + (size_t)(row - R_LEN) * D_DIM);
        } else if (MODE == 1) {
            arow[i] = (row < M_LEN) ? (A2 + (size_t)row * D_DIM)
                    : (row < MR)    ? (A1 + (size_t)(row - M_LEN) * D_DIM)
                                    : (A0 + (size_t)(row - MR) * D_DIM);
        } else {
            arow[i] = g_attn + (size_t)row * D_DIM;
        }
    }
    const float* wrow[2];
#pragma unroll
    for (int i = 0; i < 2; i++) {
        int row = bn * 128 + (tid >> 2) + 64 * i;
        wrow[i] = W + (size_t)row * K;
    }

    float acc[2][8][4];
#pragma unroll
    for (int mt = 0; mt < 2; mt++)
#pragma unroll
        for (int nt = 0; nt < 8; nt++)
#pragma unroll
            for (int i = 0; i < 4; i++) acc[mt][nt][i] = 0.f;

    float4 ra[2], rb[2];
    const int c4 = (tid & 3) * 4;

    // prologue: tile 0
#pragma unroll
    for (int i = 0; i < 2; i++) ra[i] = *(const float4*)(arow[i] + c4);
#pragma unroll
    for (int i = 0; i < 2; i++) rb[i] = *(const float4*)(wrow[i] + c4);
#pragma unroll
    for (int i = 0; i < 2; i++) {
        int r = (tid >> 2) + 64 * i;
        As[r][c4] = f2tf32(ra[i].x); As[r][c4 + 1] = f2tf32(ra[i].y);
        As[r][c4 + 2] = f2tf32(ra[i].z); As[r][c4 + 3] = f2tf32(ra[i].w);
        Bs[r][c4] = f2tf32(rb[i].x); Bs[r][c4 + 1] = f2tf32(rb[i].y);
        Bs[r][c4 + 2] = f2tf32(rb[i].z); Bs[r][c4 + 3] = f2tf32(rb[i].w);
    }
    __syncthreads();

    for (int kt = 0; kt < KT; kt++) {
        // prefetch next tile into registers (overlaps with mma)
        if (kt + 1 < KT) {
            int k0 = (kt + 1) * 16;
#pragma unroll
            for (int i = 0; i < 2; i++) ra[i] = *(const float4*)(arow[i] + k0 + c4);
#pragma unroll
            for (int i = 0; i < 2; i++) rb[i] = *(const float4*)(wrow[i] + k0 + c4);
        }
        // compute current tile
#pragma unroll
        for (int ks = 0; ks < 2; ks++) {
            int kk = ks * 8;
            unsigned b[8][2];
#pragma unroll
            for (int nt = 0; nt < 8; nt++) {
                int brow = wc * 64 + nt * 8 + grp;
                b[nt][0] = Bs[brow][kk + tig];
                b[nt][1] = Bs[brow][kk + tig + 4];
            }
#pragma unroll
            for (int mt = 0; mt < 2; mt++) {
                unsigned a[4];
                int r0 = wr * 32 + mt * 16 + grp;
                a[0] = As[r0][kk + tig];     a[1] = As[r0 + 8][kk + tig];
                a[2] = As[r0][kk + tig + 4]; a[3] = As[r0 + 8][kk + tig + 4];
#pragma unroll
                for (int nt = 0; nt < 8; nt++) mma_tf32(acc[mt][nt], a, b[nt][0], b[nt][1]);
            }
        }
        __syncthreads();
        if (kt + 1 < KT) {
#pragma unroll
            for (int i = 0; i < 2; i++) {
                int r = (tid >> 2) + 64 * i;
                As[r][c4] = f2tf32(ra[i].x); As[r][c4 + 1] = f2tf32(ra[i].y);
                As[r][c4 + 2] = f2tf32(ra[i].z); As[r][c4 + 3] = f2tf32(ra[i].w);
                Bs[r][c4] = f2tf32(rb[i].x); Bs[r][c4 + 1] = f2tf32(rb[i].y);
                Bs[r][c4 + 2] = f2tf32(rb[i].z); Bs[r][c4 + 3] = f2tf32(rb[i].w);
            }
            __syncthreads();
        }
    }

    // epilogue
#pragma unroll
    for (int mt = 0; mt < 2; mt++) {
#pragma unroll
        for (int nt = 0; nt < 8; nt++) {
            int col = bn * 128 + wc * 64 + nt * 8 + 2 * tig;
#pragma unroll
            for (int half = 0; half < 2; half++) {
                int row = bm * 128 + wr * 32 + mt * 16 + grp + half * 8;
                float v0 = acc[mt][nt][half * 2 + 0] + bias[col];
                float v1 = acc[mt][nt][half * 2 + 1] + bias[col + 1];
                if (MODE == 0) {
                    *(float2*)(g_query + (size_t)row * D_DIM + col) = make_float2(v0, v1);
                } else if (MODE == 1) {
                    int krow = (row < MR) ? row : row + L_LEN;
                    if (col < D_DIM)
                        *(float2*)(C0 + (size_t)krow * D_DIM + col) = make_float2(v0, v1);
                    else
                        *(float2*)(C1 + (size_t)krow * D_DIM + (col - D_DIM)) = make_float2(v0, v1);
                } else {
                    *(float2*)(C0 + (size_t)row * D_DIM + col) = make_float2(v0, v1);
                }
            }
        }
    }
}

// ---------------------------------------------------------------------------
// Tensor-core flash attention (tf32 mma for QK^T and P@V). Unchanged (R3-good).
// ---------------------------------------------------------------------------
#define AT_TK   64
#define AT_NT   (KVLEN / AT_TK)    // 60
#define KS_STR  68
#define VS_STR  72
#define PS_STR  72
#define SM_KS   0
#define SM_VS   (2 * 64 * KS_STR)
#define SM_PS   (SM_VS + 2 * 64 * VS_STR)
#define ATT_SMEM ((SM_PS + 8 * 16 * PS_STR) * 4)

__global__ __launch_bounds__(256, 2)
void attn_mma(const float* __restrict__ key,
              const float* __restrict__ value)
{
    extern __shared__ float sm[];
    float* Ks = sm + SM_KS;
    float* Vs = sm + SM_VS;
    float* Pw = sm + SM_PS + (threadIdx.x >> 5) * 16 * PS_STR;

    const int h   = blockIdx.x;
    const int qb  = blockIdx.y;
    const int tid = threadIdx.x;
    const int lane = tid & 31;
    const int w    = tid >> 5;
    const int grp  = lane >> 2;
    const int tig  = lane & 3;

    unsigned qa[8][4];
    {
        const float* q0 = g_query + (size_t)(qb * 128 + w * 16 + grp) * D_DIM + h * HDIM;
        const float* q1 = q0 + 8 * D_DIM;
#pragma unroll
        for (int kb = 0; kb < 8; kb++) {
            qa[kb][0] = f2tf32(q0[kb * 8 + tig] * 0.125f);
            qa[kb][1] = f2tf32(q1[kb * 8 + tig] * 0.125f);
            qa[kb][2] = f2tf32(q0[kb * 8 + tig + 4] * 0.125f);
            qa[kb][3] = f2tf32(q1[kb * 8 + tig + 4] * 0.125f);
        }
    }

    float acc[8][4];
#pragma unroll
    for (int nt = 0; nt < 8; nt++)
#pragma unroll
        for (int i = 0; i < 4; i++) acc[nt][i] = 0.f;
    float m0 = -1e30f, m1 = -1e30f, l0 = 0.f, l1 = 0.f;

    const float* kbase = key   + (size_t)h * HDIM;
    const float* vbase = value + (size_t)h * HDIM;

#pragma unroll
    for (int i = 0; i < 4; i++) {
        int idx = tid + i * 256;
        int r = idx >> 4, c = idx & 15;
        cp16(&Ks[r * KS_STR + c * 4], kbase + (size_t)r * D_DIM + c * 4);
        cp16(&Vs[r * VS_STR + c * 4], vbase + (size_t)r * D_DIM + c * 4);
    }
    CP_COMMIT();
    CP_WAIT0();
    __syncthreads();

    for (int t = 0; t < AT_NT; t++) {
        const int cur = t & 1;
        const float* Kc = Ks + cur * 64 * KS_STR;
        const float* Vc = Vs + cur * 64 * VS_STR;

        if (t + 1 < AT_NT) {
            const float* kn = kbase + (size_t)(t + 1) * AT_TK * D_DIM;
            const float* vn = vbase + (size_t)(t + 1) * AT_TK * D_DIM;
            float* Kn = Ks + (cur ^ 1) * 64 * KS_STR;
            float* Vn = Vs + (cur ^ 1) * 64 * VS_STR;
#pragma unroll
            for (int i = 0; i < 4; i++) {
                int idx = tid + i * 256;
                int r = idx >> 4, c = idx & 15;
                cp16(&Kn[r * KS_STR + c * 4], kn + (size_t)r * D_DIM + c * 4);
                cp16(&Vn[r * VS_STR + c * 4], vn + (size_t)r * D_DIM + c * 4);
            }
        }
        CP_COMMIT();

        float s[8][4];
#pragma unroll
        for (int nt = 0; nt < 8; nt++)
#pragma unroll
            for (int i = 0; i < 4; i++) s[nt][i] = 0.f;
#pragma unroll
        for (int kb = 0; kb < 8; kb++) {
#pragma unroll
            for (int nt = 0; nt < 8; nt++) {
                unsigned b0 = __float_as_uint(Kc[(nt * 8 + grp) * KS_STR + kb * 8 + tig]);
                unsigned b1 = __float_as_uint(Kc[(nt * 8 + grp) * KS_STR + kb * 8 + tig + 4]);
                mma_tf32(s[nt], qa[kb], b0, b1);
            }
        }

        float mt0 = -1e30f, mt1 = -1e30f;
#pragma unroll
        for (int nt = 0; nt < 8; nt++) {
            mt0 = fmaxf(mt0, fmaxf(s[nt][0], s[nt][1]));
            mt1 = fmaxf(mt1, fmaxf(s[nt][2], s[nt][3]));
        }
        mt0 = fmaxf(mt0, __shfl_xor_sync(0xffffffff, mt0, 1));
        mt0 = fmaxf(mt0, __shfl_xor_sync(0xffffffff, mt0, 2));
        mt1 = fmaxf(mt1, __shfl_xor_sync(0xffffffff, mt1, 1));
        mt1 = fmaxf(mt1, __shfl_xor_sync(0xffffffff, mt1, 2));

        float mn0 = fmaxf(m0, mt0), mn1 = fmaxf(m1, mt1);
        float c0 = __expf(m0 - mn0), c1 = __expf(m1 - mn1);
        l0 *= c0; l1 *= c1;
        m0 = mn0; m1 = mn1;

#pragma unroll
        for (int nt = 0; nt < 8; nt++) {
            float p00 = __expf(s[nt][0] - mn0);
            float p01 = __expf(s[nt][1] - mn0);
            float p10 = __expf(s[nt][2] - mn1);
            float p11 = __expf(s[nt][3] - mn1);
            l0 += p00 + p01;
            l1 += p10 + p11;
            *(float2*)&Pw[grp * PS_STR + nt * 8 + 2 * tig]       = make_float2(p00, p01);
            *(float2*)&Pw[(grp + 8) * PS_STR + nt * 8 + 2 * tig] = make_float2(p10, p11);
            acc[nt][0] *= c0; acc[nt][1] *= c0;
            acc[nt][2] *= c1; acc[nt][3] *= c1;
        }
        __syncwarp();

#pragma unroll
        for (int kb = 0; kb < 8; kb++) {
            unsigned a[4];
            a[0] = __float_as_uint(Pw[grp * PS_STR + kb * 8 + tig]);
            a[1] = __float_as_uint(Pw[(grp + 8) * PS_STR + kb * 8 + tig]);
            a[2] = __float_as_uint(Pw[grp * PS_STR + kb * 8 + tig + 4]);
            a[3] = __float_as_uint(Pw[(grp + 8) * PS_STR + kb * 8 + tig + 4]);
#pragma unroll
            for (int nt = 0; nt < 8; nt++) {
                unsigned b0 = __float_as_uint(Vc[(kb * 8 + tig) * VS_STR + nt * 8 + grp]);
                unsigned b1 = __float_as_uint(Vc[(kb * 8 + tig + 4) * VS_STR + nt * 8 + grp]);
                mma_tf32(acc[nt], a, b0, b1);
            }
        }

        CP_WAIT0();
        __syncthreads();
    }

    l0 += __shfl_xor_sync(0xffffffff, l0, 1);
    l0 += __shfl_xor_sync(0xffffffff, l0, 2);
    l1 += __shfl_xor_sync(0xffffffff, l1, 1);
    l1 += __shfl_xor_sync(0xffffffff, l1, 2);
    float inv0 = 1.f / l0, inv1 = 1.f / l1;

    int r0 = qb * 128 + w * 16 + grp;
    float* o0 = g_attn + (size_t)r0 * D_DIM + h * HDIM;
    float* o1 = o0 + 8 * D_DIM;
#pragma unroll
    for (int nt = 0; nt < 8; nt++) {
        int col = nt * 8 + 2 * tig;
        *(float2*)(o0 + col) = make_float2(acc[nt][0] * inv0, acc[nt][1] * inv0);
        *(float2*)(o1 + col) = make_float2(acc[nt][2] * inv1, acc[nt][3] * inv1);
    }
}

// ---------------------------------------------------------------------------
extern "C" void kernel_launch(void* const* d_in, const int* in_sizes, int n_in,
                              void* d_out, int out_size)
{
    const float* utter = (const float*)d_in[0];
    const float* rctx  = (const float*)d_in[1];
    const float* mem   = (const float*)d_in[2];
    const float* lck   = (const float*)d_in[3];
    const float* lcv   = (const float*)d_in[4];
    const float* Wq    = (const float*)d_in[5];
    const float* bq    = (const float*)d_in[6];
    const float* Wkv   = (const float*)d_in[7];
    const float* bkv   = (const float*)d_in[8];
    const float* Wo    = (const float*)d_in[9];
    const float* bo    = (const float*)d_in[10];

    float* out = (float*)d_out;                       // [2304, 1024]
    float* key = out + (size_t)QLEN * D_DIM;          // [3840, 1024]
    float* val = key + (size_t)KVLEN * D_DIM;         // [3840, 1024]

    cudaFuncSetAttribute(attn_mma, cudaFuncAttributeMaxDynamicSharedMemorySize, ATT_SMEM);

    // 1) query projection
    gemm_tf32<0><<<dim3(D_DIM / 128, QLEN / 128), 256>>>(
        utter, rctx, nullptr, Wq, bq, nullptr, nullptr);

    // 2) kv projection -> scatter into key/value
    gemm_tf32<1><<<dim3(2 * D_DIM / 128, (MR + U_LEN) / 128), 256>>>(
        utter, rctx, mem, Wkv, bkv, key, val);

    // 3) left-context splice (contiguous)
    cudaMemcpyAsync(key + (size_t)MR * D_DIM, lck,
                    (size_t)L_LEN * D_DIM * sizeof(float),
                    cudaMemcpyDeviceToDevice, 0);
    cudaMemcpyAsync(val + (size_t)MR * D_DIM, lcv,
                    (size_t)L_LEN * D_DIM * sizeof(float),
                    cudaMemcpyDeviceToDevice, 0);

    // 4) attention (tensor-core flash)
    attn_mma<<<dim3(NHEAD, QLEN / 128), 256, ATT_SMEM>>>(key, val);

    // 5) output projection
    gemm_tf32<2><<<dim3(D_DIM / 128, QLEN / 128), 256>>>(
        nullptr, nullptr, nullptr, Wo, bo, out, nullptr);
}

// round 5
// speedup vs baseline: 1.0791x; 1.0791x over previous
#include <cuda_runtime.h>
#include <cuda_bf16.h>

// Problem dims
#define U_LEN 2048
#define R_LEN 256
#define L_LEN 1024
#define M_LEN 512
#define D_DIM 1024
#define NHEAD 16
#define HDIM  64
#define QLEN  (U_LEN + R_LEN)                   // 2304
#define KVLEN (M_LEN + R_LEN + L_LEN + U_LEN)   // 3840
#define MR    (M_LEN + R_LEN)                   // 768
#define KVIN  (MR + U_LEN)                      // 2816

// Scratch (no cudaMalloc allowed) — tf32-bit staging buffers
__device__ unsigned g_kvin_t [KVIN * D_DIM];      // concat(mem,rctx,utter), tf32
__device__ unsigned g_Wq_t   [D_DIM * D_DIM];
__device__ unsigned g_Wkv_t  [2 * D_DIM * D_DIM];
__device__ unsigned g_Wo_t   [D_DIM * D_DIM];
__device__ unsigned g_query_t[QLEN * D_DIM];      // pre-scaled tf32 query
__device__ unsigned g_attn_t [QLEN * D_DIM];      // tf32 attention output

// ---------------------------------------------------------------------------
// helpers
// ---------------------------------------------------------------------------
__device__ __forceinline__ unsigned f2tf32(float f) {
    unsigned r;
    asm("cvt.rna.tf32.f32 %0, %1;" : "=r"(r) : "f"(f));
    return r;
}

__device__ __forceinline__ void mma_tf32(float* d, const unsigned* a, unsigned b0, unsigned b1) {
    asm volatile(
        "mma.sync.aligned.m16n8k8.row.col.f32.tf32.tf32.f32 "
        "{%0,%1,%2,%3}, {%4,%5,%6,%7}, {%8,%9}, {%0,%1,%2,%3};"
        : "+f"(d[0]), "+f"(d[1]), "+f"(d[2]), "+f"(d[3])
        : "r"(a[0]), "r"(a[1]), "r"(a[2]), "r"(a[3]), "r"(b0), "r"(b1));
}

__device__ __forceinline__ void cp16(void* s, const void* g) {
    unsigned sa = (unsigned)__cvta_generic_to_shared(s);
    asm volatile("cp.async.cg.shared.global [%0], [%1], 16;" :: "r"(sa), "l"(g));
}
#define CP_COMMIT() asm volatile("cp.async.commit_group;")
#define CP_WAIT0()  asm volatile("cp.async.wait_group 0;" ::: "memory")
#define CP_WAIT1()  asm volatile("cp.async.wait_group 1;" ::: "memory")

// ---------------------------------------------------------------------------
// Prepass: convert weights to tf32 (rna), grid-stride over float4
// ---------------------------------------------------------------------------
__global__ void conv_w(const float* __restrict__ src, unsigned* __restrict__ dst, int n4)
{
    int i = blockIdx.x * blockDim.x + threadIdx.x;
    for (; i < n4; i += gridDim.x * blockDim.x) {
        float4 v = ((const float4*)src)[i];
        uint4 o;
        o.x = f2tf32(v.x); o.y = f2tf32(v.y); o.z = f2tf32(v.z); o.w = f2tf32(v.w);
        ((uint4*)dst)[i] = o;
    }
}

// Prepass: gather concat(mem, rctx, utter) + convert -> g_kvin_t
__global__ void conv_kvin(const float* __restrict__ utter,
                          const float* __restrict__ rctx,
                          const float* __restrict__ mem)
{
    int i = blockIdx.x * blockDim.x + threadIdx.x;          // float4 index
    const int n4 = KVIN * D_DIM / 4;
    for (; i < n4; i += gridDim.x * blockDim.x) {
        int row = i / (D_DIM / 4);
        int c4  = i % (D_DIM / 4);
        const float4* src = (row < M_LEN)
            ? (const float4*)(mem + (size_t)row * D_DIM) + c4
            : (row < MR)
            ? (const float4*)(rctx + (size_t)(row - M_LEN) * D_DIM) + c4
            : (const float4*)(utter + (size_t)(row - MR) * D_DIM) + c4;
        float4 v = *src;
        uint4 o;
        o.x = f2tf32(v.x); o.y = f2tf32(v.y); o.z = f2tf32(v.z); o.w = f2tf32(v.w);
        ((uint4*)g_kvin_t)[i] = o;
    }
}

// ---------------------------------------------------------------------------
// TF32 GEMM, pre-converted operands: C[M,N] = A_t[M,K] @ W_t[N,K]^T + bias
// BM=128, BN=128, BK=16, 256 threads (8 warps 4x2), warp=32x64.
// cp.async 3-stage pipeline, ONE syncthreads per k-tile, zero cvt in loop.
// MODE 0: A=g_kvin_t+MR rows (q_in) -> g_query_t (tf32, pre-scaled)
// MODE 1: A=g_kvin_t               -> key/value fp32 scatter (N=2048)
// MODE 2: A=g_attn_t               -> out fp32
// ---------------------------------------------------------------------------
#define GKT (D_DIM / 16)   // 64

template <int MODE>
__global__ __launch_bounds__(256, 2)
void gemm_pc(const float* __restrict__ bias,
             float* __restrict__ C0,
             float* __restrict__ C1)
{
    __shared__ unsigned As[3][128][20];
    __shared__ unsigned Bs[3][128][20];

    const int tid  = threadIdx.x;
    const int lane = tid & 31;
    const int warp = tid >> 5;
    const int wr   = warp & 3;
    const int wc   = warp >> 2;
    const int bm = blockIdx.y, bn = blockIdx.x;
    const int tig = lane & 3, grp = lane >> 2;

    const unsigned* A = (MODE == 0) ? (g_kvin_t + (size_t)M_LEN * D_DIM)
                      : (MODE == 1) ? g_kvin_t
                                    : g_attn_t;
    const unsigned* W = (MODE == 0) ? g_Wq_t
                      : (MODE == 1) ? g_Wkv_t
                                    : g_Wo_t;

    // this thread's 2 A-chunks + 2 B-chunks per tile: idx = tid + i*256 over 512
    // chunk -> row = idx>>2, c4 = (idx&3)*4
    const unsigned* aptr[2];
    const unsigned* wptr[2];
    int srow[2], sc4[2];
#pragma unroll
    for (int i = 0; i < 2; i++) {
        int idx = tid + i * 256;
        srow[i] = idx >> 2;
        sc4[i]  = (idx & 3) * 4;
        aptr[i] = A + (size_t)(bm * 128 + srow[i]) * D_DIM + sc4[i];
        wptr[i] = W + (size_t)(bn * 128 + srow[i]) * D_DIM + sc4[i];
    }

    float acc[2][8][4];
#pragma unroll
    for (int mt = 0; mt < 2; mt++)
#pragma unroll
        for (int nt = 0; nt < 8; nt++)
#pragma unroll
            for (int i = 0; i < 4; i++) acc[mt][nt][i] = 0.f;

    // prologue: tiles 0,1 -> bufs 0,1
#pragma unroll
    for (int t = 0; t < 2; t++) {
#pragma unroll
        for (int i = 0; i < 2; i++) {
            cp16(&As[t][srow[i]][sc4[i]], aptr[i] + t * 16);
            cp16(&Bs[t][srow[i]][sc4[i]], wptr[i] + t * 16);
        }
        CP_COMMIT();
    }

    for (int kt = 0; kt < GKT; kt++) {
        const int cur = kt % 3;
        CP_WAIT1();                 // tile kt landed
        __syncthreads();            // all see it; all done reading buf (kt+2)%3

        // issue tile kt+2 into buf (kt+2)%3
        if (kt + 2 < GKT) {
            const int nxt = (kt + 2) % 3;
            int k0 = (kt + 2) * 16;
#pragma unroll
            for (int i = 0; i < 2; i++) {
                cp16(&As[nxt][srow[i]][sc4[i]], aptr[i] + k0);
                cp16(&Bs[nxt][srow[i]][sc4[i]], wptr[i] + k0);
            }
        }
        CP_COMMIT();

        // compute tile kt
#pragma unroll
        for (int ks = 0; ks < 2; ks++) {
            int kk = ks * 8;
            unsigned b[8][2];
#pragma unroll
            for (int nt = 0; nt < 8; nt++) {
                int brow = wc * 64 + nt * 8 + grp;
                b[nt][0] = Bs[cur][brow][kk + tig];
                b[nt][1] = Bs[cur][brow][kk + tig + 4];
            }
#pragma unroll
            for (int mt = 0; mt < 2; mt++) {
                unsigned a[4];
                int r0 = wr * 32 + mt * 16 + grp;
                a[0] = As[cur][r0][kk + tig];     a[1] = As[cur][r0 + 8][kk + tig];
                a[2] = As[cur][r0][kk + tig + 4]; a[3] = As[cur][r0 + 8][kk + tig + 4];
#pragma unroll
                for (int nt = 0; nt < 8; nt++) mma_tf32(acc[mt][nt], a, b[nt][0], b[nt][1]);
            }
        }
    }

    // epilogue
#pragma unroll
    for (int mt = 0; mt < 2; mt++) {
#pragma unroll
        for (int nt = 0; nt < 8; nt++) {
            int col = bn * 128 + wc * 64 + nt * 8 + 2 * tig;
#pragma unroll
            for (int half = 0; half < 2; half++) {
                int row = bm * 128 + wr * 32 + mt * 16 + grp + half * 8;
                float v0 = acc[mt][nt][half * 2 + 0] + bias[col];
                float v1 = acc[mt][nt][half * 2 + 1] + bias[col + 1];
                if (MODE == 0) {
                    // pre-scaled tf32 query
                    uint2 o = make_uint2(f2tf32(v0 * 0.125f), f2tf32(v1 * 0.125f));
                    *(uint2*)(g_query_t + (size_t)row * D_DIM + col) = o;
                } else if (MODE == 1) {
                    int krow = (row < MR) ? row : row + L_LEN;
                    if (col < D_DIM)
                        *(float2*)(C0 + (size_t)krow * D_DIM + col) = make_float2(v0, v1);
                    else
                        *(float2*)(C1 + (size_t)krow * D_DIM + (col - D_DIM)) = make_float2(v0, v1);
                } else {
                    *(float2*)(C0 + (size_t)row * D_DIM + col) = make_float2(v0, v1);
                }
            }
        }
    }
}

// ---------------------------------------------------------------------------
// Tensor-core flash attention (tf32 mma). Same structure as R3 (known good);
// q from g_query_t (pre-scaled tf32), output written as tf32 to g_attn_t.
// ---------------------------------------------------------------------------
#define AT_TK   64
#define AT_NT   (KVLEN / AT_TK)    // 60
#define KS_STR  68
#define VS_STR  72
#define PS_STR  72
#define SM_KS   0
#define SM_VS   (2 * 64 * KS_STR)
#define SM_PS   (SM_VS + 2 * 64 * VS_STR)
#define ATT_SMEM ((SM_PS + 8 * 16 * PS_STR) * 4)

__global__ __launch_bounds__(256, 2)
void attn_mma(const float* __restrict__ key,
              const float* __restrict__ value)
{
    extern __shared__ float sm[];
    float* Ks = sm + SM_KS;
    float* Vs = sm + SM_VS;
    float* Pw = sm + SM_PS + (threadIdx.x >> 5) * 16 * PS_STR;

    const int h   = blockIdx.x;
    const int qb  = blockIdx.y;
    const int tid = threadIdx.x;
    const int lane = tid & 31;
    const int w    = tid >> 5;
    const int grp  = lane >> 2;
    const int tig  = lane & 3;

    unsigned qa[8][4];
    {
        const unsigned* q0 = g_query_t + (size_t)(qb * 128 + w * 16 + grp) * D_DIM + h * HDIM;
        const unsigned* q1 = q0 + 8 * D_DIM;
#pragma unroll
        for (int kb = 0; kb < 8; kb++) {
            qa[kb][0] = q0[kb * 8 + tig];
            qa[kb][1] = q1[kb * 8 + tig];
            qa[kb][2] = q0[kb * 8 + tig + 4];
            qa[kb][3] = q1[kb * 8 + tig + 4];
        }
    }

    float acc[8][4];
#pragma unroll
    for (int nt = 0; nt < 8; nt++)
#pragma unroll
        for (int i = 0; i < 4; i++) acc[nt][i] = 0.f;
    float m0 = -1e30f, m1 = -1e30f, l0 = 0.f, l1 = 0.f;

    const float* kbase = key   + (size_t)h * HDIM;
    const float* vbase = value + (size_t)h * HDIM;

#pragma unroll
    for (int i = 0; i < 4; i++) {
        int idx = tid + i * 256;
        int r = idx >> 4, c = idx & 15;
        cp16(&Ks[r * KS_STR + c * 4], kbase + (size_t)r * D_DIM + c * 4);
        cp16(&Vs[r * VS_STR + c * 4], vbase + (size_t)r * D_DIM + c * 4);
    }
    CP_COMMIT();
    CP_WAIT0();
    __syncthreads();

    for (int t = 0; t < AT_NT; t++) {
        const int cur = t & 1;
        const float* Kc = Ks + cur * 64 * KS_STR;
        const float* Vc = Vs + cur * 64 * VS_STR;

        if (t + 1 < AT_NT) {
            const float* kn = kbase + (size_t)(t + 1) * AT_TK * D_DIM;
            const float* vn = vbase + (size_t)(t + 1) * AT_TK * D_DIM;
            float* Kn = Ks + (cur ^ 1) * 64 * KS_STR;
            float* Vn = Vs + (cur ^ 1) * 64 * VS_STR;
#pragma unroll
            for (int i = 0; i < 4; i++) {
                int idx = tid + i * 256;
                int r = idx >> 4, c = idx & 15;
                cp16(&Kn[r * KS_STR + c * 4], kn + (size_t)r * D_DIM + c * 4);
                cp16(&Vn[r * VS_STR + c * 4], vn + (size_t)r * D_DIM + c * 4);
            }
        }
        CP_COMMIT();

        float s[8][4];
#pragma unroll
        for (int nt = 0; nt < 8; nt++)
#pragma unroll
            for (int i = 0; i < 4; i++) s[nt][i] = 0.f;
#pragma unroll
        for (int kb = 0; kb < 8; kb++) {
#pragma unroll
            for (int nt = 0; nt < 8; nt++) {
                unsigned b0 = __float_as_uint(Kc[(nt * 8 + grp) * KS_STR + kb * 8 + tig]);
                unsigned b1 = __float_as_uint(Kc[(nt * 8 + grp) * KS_STR + kb * 8 + tig + 4]);
                mma_tf32(s[nt], qa[kb], b0, b1);
            }
        }

        float mt0 = -1e30f, mt1 = -1e30f;
#pragma unroll
        for (int nt = 0; nt < 8; nt++) {
            mt0 = fmaxf(mt0, fmaxf(s[nt][0], s[nt][1]));
            mt1 = fmaxf(mt1, fmaxf(s[nt][2], s[nt][3]));
        }
        mt0 = fmaxf(mt0, __shfl_xor_sync(0xffffffff, mt0, 1));
        mt0 = fmaxf(mt0, __shfl_xor_sync(0xffffffff, mt0, 2));
        mt1 = fmaxf(mt1, __shfl_xor_sync(0xffffffff, mt1, 1));
        mt1 = fmaxf(mt1, __shfl_xor_sync(0xffffffff, mt1, 2));

        float mn0 = fmaxf(m0, mt0), mn1 = fmaxf(m1, mt1);
        float c0 = __expf(m0 - mn0), c1 = __expf(m1 - mn1);
        l0 *= c0; l1 *= c1;
        m0 = mn0; m1 = mn1;

#pragma unroll
        for (int nt = 0; nt < 8; nt++) {
            float p00 = __expf(s[nt][0] - mn0);
            float p01 = __expf(s[nt][1] - mn0);
            float p10 = __expf(s[nt][2] - mn1);
            float p11 = __expf(s[nt][3] - mn1);
            l0 += p00 + p01;
            l1 += p10 + p11;
            *(float2*)&Pw[grp * PS_STR + nt * 8 + 2 * tig]       = make_float2(p00, p01);
            *(float2*)&Pw[(grp + 8) * PS_STR + nt * 8 + 2 * tig] = make_float2(p10, p11);
            acc[nt][0] *= c0; acc[nt][1] *= c0;
            acc[nt][2] *= c1; acc[nt][3] *= c1;
        }
        __syncwarp();

#pragma unroll
        for (int kb = 0; kb < 8; kb++) {
            unsigned a[4];
            a[0] = __float_as_uint(Pw[grp * PS_STR + kb * 8 + tig]);
            a[1] = __float_as_uint(Pw[(grp + 8) * PS_STR + kb * 8 + tig]);
            a[2] = __float_as_uint(Pw[grp * PS_STR + kb * 8 + tig + 4]);
            a[3] = __float_as_uint(Pw[(grp + 8) * PS_STR + kb * 8 + tig + 4]);
#pragma unroll
            for (int nt = 0; nt < 8; nt++) {
                unsigned b0 = __float_as_uint(Vc[(kb * 8 + tig) * VS_STR + nt * 8 + grp]);
                unsigned b1 = __float_as_uint(Vc[(kb * 8 + tig + 4) * VS_STR + nt * 8 + grp]);
                mma_tf32(acc[nt], a, b0, b1);
            }
        }

        CP_WAIT0();
        __syncthreads();
    }

    l0 += __shfl_xor_sync(0xffffffff, l0, 1);
    l0 += __shfl_xor_sync(0xffffffff, l0, 2);
    l1 += __shfl_xor_sync(0xffffffff, l1, 1);
    l1 += __shfl_xor_sync(0xffffffff, l1, 2);
    float inv0 = 1.f / l0, inv1 = 1.f / l1;

    int r0 = qb * 128 + w * 16 + grp;
    unsigned* o0 = g_attn_t + (size_t)r0 * D_DIM + h * HDIM;
    unsigned* o1 = o0 + 8 * D_DIM;
#pragma unroll
    for (int nt = 0; nt < 8; nt++) {
        int col = nt * 8 + 2 * tig;
        *(uint2*)(o0 + col) = make_uint2(f2tf32(acc[nt][0] * inv0), f2tf32(acc[nt][1] * inv0));
        *(uint2*)(o1 + col) = make_uint2(f2tf32(acc[nt][2] * inv1), f2tf32(acc[nt][3] * inv1));
    }
}

// ---------------------------------------------------------------------------
extern "C" void kernel_launch(void* const* d_in, const int* in_sizes, int n_in,
                              void* d_out, int out_size)
{
    const float* utter = (const float*)d_in[0];
    const float* rctx  = (const float*)d_in[1];
    const float* mem   = (const float*)d_in[2];
    const float* lck   = (const float*)d_in[3];
    const float* lcv   = (const float*)d_in[4];
    const float* Wq    = (const float*)d_in[5];
    const float* bq    = (const float*)d_in[6];
    const float* Wkv   = (const float*)d_in[7];
    const float* bkv   = (const float*)d_in[8];
    const float* Wo    = (const float*)d_in[9];
    const float* bo    = (const float*)d_in[10];

    float* out = (float*)d_out;                       // [2304, 1024]
    float* key = out + (size_t)QLEN * D_DIM;          // [3840, 1024]
    float* val = key + (size_t)KVLEN * D_DIM;         // [3840, 1024]

    cudaFuncSetAttribute(attn_mma, cudaFuncAttributeMaxDynamicSharedMemorySize, ATT_SMEM);

    unsigned* wq_t, *wkv_t, *wo_t;
    cudaGetSymbolAddress((void**)&wq_t,  g_Wq_t);
    cudaGetSymbolAddress((void**)&wkv_t, g_Wkv_t);
    cudaGetSymbolAddress((void**)&wo_t,  g_Wo_t);

    // 0) prepass conversions (tf32, rna)
    conv_w<<<256, 256>>>(Wq,  wq_t,  D_DIM * D_DIM / 4);
    conv_w<<<512, 256>>>(Wkv, wkv_t, 2 * D_DIM * D_DIM / 4);
    conv_w<<<256, 256>>>(Wo,  wo_t,  D_DIM * D_DIM / 4);
    conv_kvin<<<512, 256>>>(utter, rctx, mem);

    // 1) query projection -> g_query_t (pre-scaled tf32)
    gemm_pc<0><<<dim3(D_DIM / 128, QLEN / 128), 256>>>(bq, nullptr, nullptr);

    // 2) kv projection -> scatter into key/value (fp32 outputs)
    gemm_pc<1><<<dim3(2 * D_DIM / 128, KVIN / 128), 256>>>(bkv, key, val);

    // 3) left-context splice (contiguous)
    cudaMemcpyAsync(key + (size_t)MR * D_DIM, lck,
                    (size_t)L_LEN * D_DIM * sizeof(float),
                    cudaMemcpyDeviceToDevice, 0);
    cudaMemcpyAsync(val + (size_t)MR * D_DIM, lcv,
                    (size_t)L_LEN * D_DIM * sizeof(float),
                    cudaMemcpyDeviceToDevice, 0);

    // 4) attention (tensor-core flash) -> g_attn_t (tf32)
    attn_mma<<<dim3(NHEAD, QLEN / 128), 256, ATT_SMEM>>>(key, val);

    // 5) output projection
    gemm_pc<2><<<dim3(D_DIM / 128, QLEN / 128), 256>>>(bo, out, nullptr);
}

// round 6
// speedup vs baseline: 1.2719x; 1.1786x over previous
#include <cuda_runtime.h>

// Problem dims
#define U_LEN 2048
#define R_LEN 256
#define L_LEN 1024
#define M_LEN 512
#define D_DIM 1024
#define NHEAD 16
#define HDIM  64
#define QLEN  (U_LEN + R_LEN)                   // 2304
#define KVLEN (M_LEN + R_LEN + L_LEN + U_LEN)   // 3840
#define MR    (M_LEN + R_LEN)                   // 768
#define KVIN  (MR + U_LEN)                      // 2816

// blocked tile: 128 rows x 16 k (+4 pad) = 2560 words = 10240 B
#define BLKW   2560
#define TILEB  10240
#define NKT    (D_DIM / 16)      // 64 k-tiles

// head-major padded K/V
#define KHS_STR 68
#define VHS_STR 72
#define KHS_HEAD (KVLEN * KHS_STR)   // 261120
#define VHS_HEAD (KVLEN * VHS_STR)   // 276480

// Scratch (no cudaMalloc allowed)
__device__ unsigned g_kvin_blk[22 * 64 * BLKW];
__device__ unsigned g_Wq_blk  [ 8 * 64 * BLKW];
__device__ unsigned g_Wkv_blk [16 * 64 * BLKW];
__device__ unsigned g_Wo_blk  [ 8 * 64 * BLKW];
__device__ unsigned g_attn_blk[18 * 64 * BLKW];
__device__ unsigned g_query_t [QLEN * D_DIM];        // pre-scaled tf32 query
__device__ float    g_key_hs  [NHEAD * KHS_HEAD];    // head-major padded K (fp32 bits)
__device__ float    g_val_hs  [NHEAD * VHS_HEAD];    // head-major padded V

// ---------------------------------------------------------------------------
// helpers
// ---------------------------------------------------------------------------
__device__ __forceinline__ unsigned f2tf32(float f) {
    unsigned r;
    asm("cvt.rna.tf32.f32 %0, %1;" : "=r"(r) : "f"(f));
    return r;
}

__device__ __forceinline__ void mma_tf32(float* d, const unsigned* a, unsigned b0, unsigned b1) {
    asm volatile(
        "mma.sync.aligned.m16n8k8.row.col.f32.tf32.tf32.f32 "
        "{%0,%1,%2,%3}, {%4,%5,%6,%7}, {%8,%9}, {%0,%1,%2,%3};"
        : "+f"(d[0]), "+f"(d[1]), "+f"(d[2]), "+f"(d[3])
        : "r"(a[0]), "r"(a[1]), "r"(a[2]), "r"(a[3]), "r"(b0), "r"(b1));
}

__device__ __forceinline__ unsigned smaddr(const void* p) {
    return (unsigned)__cvta_generic_to_shared(p);
}
__device__ __forceinline__ void mbar_init(unsigned a) {
    asm volatile("mbarrier.init.shared.b64 [%0], 1;" :: "r"(a) : "memory");
}
__device__ __forceinline__ void mbar_expect(unsigned a, unsigned tx) {
    asm volatile("mbarrier.arrive.expect_tx.shared.b64 _, [%0], %1;" :: "r"(a), "r"(tx) : "memory");
}
__device__ __forceinline__ void bulk_g2s(unsigned sdst, const void* gsrc, unsigned bytes, unsigned mbar) {
    asm volatile("cp.async.bulk.shared::cta.global.mbarrier::complete_tx::bytes [%0], [%1], %2, [%3];"
                 :: "r"(sdst), "l"(gsrc), "r"(bytes), "r"(mbar) : "memory");
}
__device__ __forceinline__ void mbar_wait(unsigned a, unsigned ph) {
    asm volatile(
        "{\n\t.reg .pred P;\n\t"
        "WL%=:\n\t"
        "mbarrier.try_wait.parity.acquire.cta.shared::cta.b64 P, [%0], %1, 0x989680;\n\t"
        "@P bra WD%=;\n\t"
        "bra WL%=;\n\t"
        "WD%=:\n\t}"
        :: "r"(a), "r"(ph) : "memory");
}

// ---------------------------------------------------------------------------
// Prepass: weights -> blocked tf32 tiles. rows = N, cols = K=1024.
// ---------------------------------------------------------------------------
__global__ void conv_w_blk(const float* __restrict__ src, unsigned* __restrict__ dst, int n4)
{
    int i = blockIdx.x * blockDim.x + threadIdx.x;
    for (; i < n4; i += gridDim.x * blockDim.x) {
        int row = i >> 8;                  // /256 (1024/4)
        int col = (i & 255) * 4;
        float4 v = ((const float4*)src)[i];
        uint4 o;
        o.x = f2tf32(v.x); o.y = f2tf32(v.y); o.z = f2tf32(v.z); o.w = f2tf32(v.w);
        size_t off = ((size_t)(row >> 7) * 64 + (col >> 4)) * BLKW + (row & 127) * 20 + (col & 15);
        *(uint4*)(dst + off) = o;
    }
}

// Prepass: gather concat(mem, rctx, utter) -> blocked tf32
__global__ void conv_kvin_blk(const float* __restrict__ utter,
                              const float* __restrict__ rctx,
                              const float* __restrict__ mem)
{
    int i = blockIdx.x * blockDim.x + threadIdx.x;
    const int n4 = KVIN * D_DIM / 4;
    for (; i < n4; i += gridDim.x * blockDim.x) {
        int row = i >> 8;
        int col = (i & 255) * 4;
        const float4* s = (row < M_LEN)
            ? (const float4*)(mem + (size_t)row * D_DIM + col)
            : (row < MR)
            ? (const float4*)(rctx + (size_t)(row - M_LEN) * D_DIM + col)
            : (const float4*)(utter + (size_t)(row - MR) * D_DIM + col);
        float4 v = *s;
        uint4 o;
        o.x = f2tf32(v.x); o.y = f2tf32(v.y); o.z = f2tf32(v.z); o.w = f2tf32(v.w);
        size_t off = ((size_t)(row >> 7) * 64 + (col >> 4)) * BLKW + (row & 127) * 20 + (col & 15);
        *(uint4*)(g_kvin_blk + off) = o;
    }
}

// Prepass: left-context rows into head-major padded K/V (raw fp32 bits)
__global__ void conv_lc(const float* __restrict__ lck, const float* __restrict__ lcv)
{
    int i = blockIdx.x * blockDim.x + threadIdx.x;
    const int n4 = L_LEN * D_DIM / 4;
    for (; i < n4; i += gridDim.x * blockDim.x) {
        int row = i >> 8;
        int col = (i & 255) * 4;
        int head = col >> 6, c = col & 63;
        float4 k4 = *(const float4*)(lck + (size_t)row * D_DIM + col);
        float4 v4 = *(const float4*)(lcv + (size_t)row * D_DIM + col);
        *(float4*)(g_key_hs + (size_t)head * KHS_HEAD + (size_t)(MR + row) * KHS_STR + c) = k4;
        *(float4*)(g_val_hs + (size_t)head * VHS_HEAD + (size_t)(MR + row) * VHS_STR + c) = v4;
    }
}

// ---------------------------------------------------------------------------
// TF32 GEMM with bulk-copy pipeline: C[M,N] = A_blk @ W_blk^T + bias
// BM=BN=128, BK=16, 256 threads (8 warps 4x2), 3-stage mbarrier pipeline.
// MODE 0: A=kvin blocks 4..21 (q_in)  -> g_query_t (tf32 pre-scaled)
// MODE 1: A=kvin blocks 0..21        -> key/value fp32 + head-major copies
// MODE 2: A=g_attn_blk               -> out fp32
// ---------------------------------------------------------------------------
#define GEMM_SMEM (6 * BLKW * 4 + 32)

template <int MODE>
__global__ __launch_bounds__(256, 2)
void gemm_blk(const float* __restrict__ bias,
              float* __restrict__ C0,
              float* __restrict__ C1)
{
    extern __shared__ unsigned gsm[];
    unsigned* As = gsm;               // [3][2560]
    unsigned* Bs = gsm + 3 * BLKW;    // [3][2560]
    const unsigned mb0 = smaddr(gsm + 6 * BLKW);   // 3 mbarriers, 8B apart

    const int tid  = threadIdx.x;
    const int lane = tid & 31;
    const int warp = tid >> 5;
    const int wr   = warp & 3;
    const int wc   = warp >> 2;
    const int bm = blockIdx.y, bn = blockIdx.x;
    const int tig = lane & 3, grp = lane >> 2;

    const unsigned* Ab =
        (MODE == 0) ? g_kvin_blk + (size_t)(bm + 4) * 64 * BLKW
      : (MODE == 1) ? g_kvin_blk + (size_t)bm * 64 * BLKW
                    : g_attn_blk + (size_t)bm * 64 * BLKW;
    const unsigned* Wb =
        ((MODE == 0) ? g_Wq_blk : (MODE == 1) ? g_Wkv_blk : g_Wo_blk)
        + (size_t)bn * 64 * BLKW;

    if (tid == 0) {
        mbar_init(mb0); mbar_init(mb0 + 8); mbar_init(mb0 + 16);
    }
    __syncthreads();
    if (tid == 0) {
#pragma unroll
        for (int s = 0; s < 3; s++) {
            mbar_expect(mb0 + 8 * s, 2 * TILEB);
            bulk_g2s(smaddr(As + s * BLKW), Ab + (size_t)s * BLKW, TILEB, mb0 + 8 * s);
            bulk_g2s(smaddr(Bs + s * BLKW), Wb + (size_t)s * BLKW, TILEB, mb0 + 8 * s);
        }
    }

    float acc[2][8][4];
#pragma unroll
    for (int mt = 0; mt < 2; mt++)
#pragma unroll
        for (int nt = 0; nt < 8; nt++)
#pragma unroll
            for (int i = 0; i < 4; i++) acc[mt][nt][i] = 0.f;

    for (int kt = 0; kt < NKT; kt++) {
        const int s = kt % 3;
        const unsigned ph = (unsigned)((kt / 3) & 1);
        mbar_wait(mb0 + 8 * s, ph);

        const unsigned* Asl = As + s * BLKW;
        const unsigned* Bsl = Bs + s * BLKW;
#pragma unroll
        for (int ks = 0; ks < 2; ks++) {
            int kk = ks * 8;
            unsigned b[8][2];
#pragma unroll
            for (int nt = 0; nt < 8; nt++) {
                int brow = wc * 64 + nt * 8 + grp;
                b[nt][0] = Bsl[brow * 20 + kk + tig];
                b[nt][1] = Bsl[brow * 20 + kk + tig + 4];
            }
#pragma unroll
            for (int mt = 0; mt < 2; mt++) {
                unsigned a[4];
                int r0 = wr * 32 + mt * 16 + grp;
                a[0] = Asl[r0 * 20 + kk + tig];       a[1] = Asl[(r0 + 8) * 20 + kk + tig];
                a[2] = Asl[r0 * 20 + kk + tig + 4];   a[3] = Asl[(r0 + 8) * 20 + kk + tig + 4];
#pragma unroll
                for (int nt = 0; nt < 8; nt++) mma_tf32(acc[mt][nt], a, b[nt][0], b[nt][1]);
            }
        }
        __syncthreads();
        if (tid == 0 && kt + 3 < NKT) {
            mbar_expect(mb0 + 8 * s, 2 * TILEB);
            bulk_g2s(smaddr(As + s * BLKW), Ab + (size_t)(kt + 3) * BLKW, TILEB, mb0 + 8 * s);
            bulk_g2s(smaddr(Bs + s * BLKW), Wb + (size_t)(kt + 3) * BLKW, TILEB, mb0 + 8 * s);
        }
    }

    // epilogue
#pragma unroll
    for (int mt = 0; mt < 2; mt++) {
#pragma unroll
        for (int nt = 0; nt < 8; nt++) {
            int col = bn * 128 + wc * 64 + nt * 8 + 2 * tig;
#pragma unroll
            for (int half = 0; half < 2; half++) {
                int row = bm * 128 + wr * 32 + mt * 16 + grp + half * 8;
                float v0 = acc[mt][nt][half * 2 + 0] + bias[col];
                float v1 = acc[mt][nt][half * 2 + 1] + bias[col + 1];
                if (MODE == 0) {
                    uint2 o = make_uint2(f2tf32(v0 * 0.125f), f2tf32(v1 * 0.125f));
                    *(uint2*)(g_query_t + (size_t)row * D_DIM + col) = o;
                } else if (MODE == 1) {
                    int krow = (row < MR) ? row : row + L_LEN;
                    if (col < D_DIM) {
                        *(float2*)(C0 + (size_t)krow * D_DIM + col) = make_float2(v0, v1);
                        *(float2*)(g_key_hs + (size_t)(col >> 6) * KHS_HEAD
                                   + (size_t)krow * KHS_STR + (col & 63)) = make_float2(v0, v1);
                    } else {
                        int vc = col - D_DIM;
                        *(float2*)(C1 + (size_t)krow * D_DIM + vc) = make_float2(v0, v1);
                        *(float2*)(g_val_hs + (size_t)(vc >> 6) * VHS_HEAD
                                   + (size_t)krow * VHS_STR + (vc & 63)) = make_float2(v0, v1);
                    }
                } else {
                    *(float2*)(C0 + (size_t)row * D_DIM + col) = make_float2(v0, v1);
                }
            }
        }
    }
}

// ---------------------------------------------------------------------------
// Tensor-core flash attention, 512 threads = 256 q rows of one head.
// K/V tiles (64 keys) loaded via single cp.async.bulk each, 3-stage pipeline.
// Warp w owns rows [w*16, w*16+16). Per-warp math identical to R5.
// ---------------------------------------------------------------------------
#define AT_TK   64
#define AT_NT   (KVLEN / AT_TK)    // 60
#define KTILE_F (AT_TK * KHS_STR)  // 4352 floats = 17408 B
#define VTILE_F (AT_TK * VHS_STR)  // 4608 floats = 18432 B
#define PS_STR  72
#define ATT_SMEM ((3 * KTILE_F + 3 * VTILE_F + 16 * 16 * PS_STR) * 4 + 32)

__global__ __launch_bounds__(512, 1)
void attn_mma(int dummy)
{
    extern __shared__ float sm[];
    float* Ks = sm;                              // [3][4352]
    float* Vs = sm + 3 * KTILE_F;                // [3][4608]
    float* Pa = sm + 3 * KTILE_F + 3 * VTILE_F;  // [16][16*72]
    const unsigned mb0 = smaddr(Pa + 16 * 16 * PS_STR);

    const int h   = blockIdx.x;
    const int qb  = blockIdx.y;
    const int tid = threadIdx.x;
    const int lane = tid & 31;
    const int w    = tid >> 5;
    const int grp  = lane >> 2;
    const int tig  = lane & 3;
    float* Pw = Pa + w * 16 * PS_STR;

    const float* ksrc = g_key_hs + (size_t)h * KHS_HEAD;
    const float* vsrc = g_val_hs + (size_t)h * VHS_HEAD;

    if (tid == 0) {
        mbar_init(mb0); mbar_init(mb0 + 8); mbar_init(mb0 + 16);
    }
    __syncthreads();
    if (tid == 0) {
#pragma unroll
        for (int s = 0; s < 3; s++) {
            mbar_expect(mb0 + 8 * s, 17408 + 18432);
            bulk_g2s(smaddr(Ks + s * KTILE_F), ksrc + (size_t)s * KTILE_F, 17408, mb0 + 8 * s);
            bulk_g2s(smaddr(Vs + s * VTILE_F), vsrc + (size_t)s * VTILE_F, 18432, mb0 + 8 * s);
        }
    }

    // Q fragments (pre-scaled tf32)
    unsigned qa[8][4];
    {
        const unsigned* q0 = g_query_t + (size_t)(qb * 256 + w * 16 + grp) * D_DIM + h * HDIM;
        const unsigned* q1 = q0 + 8 * D_DIM;
#pragma unroll
        for (int kb = 0; kb < 8; kb++) {
            qa[kb][0] = q0[kb * 8 + tig];
            qa[kb][1] = q1[kb * 8 + tig];
            qa[kb][2] = q0[kb * 8 + tig + 4];
            qa[kb][3] = q1[kb * 8 + tig + 4];
        }
    }

    float acc[8][4];
#pragma unroll
    for (int nt = 0; nt < 8; nt++)
#pragma unroll
        for (int i = 0; i < 4; i++) acc[nt][i] = 0.f;
    float m0 = -1e30f, m1 = -1e30f, l0 = 0.f, l1 = 0.f;

    for (int t = 0; t < AT_NT; t++) {
        const int s = t % 3;
        const unsigned ph = (unsigned)((t / 3) & 1);
        mbar_wait(mb0 + 8 * s, ph);

        const float* Kc = Ks + s * KTILE_F;
        const float* Vc = Vs + s * VTILE_F;

        // ---- S = Q K^T ----
        float sc[8][4];
#pragma unroll
        for (int nt = 0; nt < 8; nt++)
#pragma unroll
            for (int i = 0; i < 4; i++) sc[nt][i] = 0.f;
#pragma unroll
        for (int kb = 0; kb < 8; kb++) {
#pragma unroll
            for (int nt = 0; nt < 8; nt++) {
                unsigned b0 = __float_as_uint(Kc[(nt * 8 + grp) * KHS_STR + kb * 8 + tig]);
                unsigned b1 = __float_as_uint(Kc[(nt * 8 + grp) * KHS_STR + kb * 8 + tig + 4]);
                mma_tf32(sc[nt], qa[kb], b0, b1);
            }
        }

        // ---- online softmax ----
        float mt0 = -1e30f, mt1 = -1e30f;
#pragma unroll
        for (int nt = 0; nt < 8; nt++) {
            mt0 = fmaxf(mt0, fmaxf(sc[nt][0], sc[nt][1]));
            mt1 = fmaxf(mt1, fmaxf(sc[nt][2], sc[nt][3]));
        }
        mt0 = fmaxf(mt0, __shfl_xor_sync(0xffffffff, mt0, 1));
        mt0 = fmaxf(mt0, __shfl_xor_sync(0xffffffff, mt0, 2));
        mt1 = fmaxf(mt1, __shfl_xor_sync(0xffffffff, mt1, 1));
        mt1 = fmaxf(mt1, __shfl_xor_sync(0xffffffff, mt1, 2));

        float mn0 = fmaxf(m0, mt0), mn1 = fmaxf(m1, mt1);
        float c0 = __expf(m0 - mn0), c1 = __expf(m1 - mn1);
        l0 *= c0; l1 *= c1;
        m0 = mn0; m1 = mn1;

#pragma unroll
        for (int nt = 0; nt < 8; nt++) {
            float p00 = __expf(sc[nt][0] - mn0);
            float p01 = __expf(sc[nt][1] - mn0);
            float p10 = __expf(sc[nt][2] - mn1);
            float p11 = __expf(sc[nt][3] - mn1);
            l0 += p00 + p01;
            l1 += p10 + p11;
            *(float2*)&Pw[grp * PS_STR + nt * 8 + 2 * tig]       = make_float2(p00, p01);
            *(float2*)&Pw[(grp + 8) * PS_STR + nt * 8 + 2 * tig] = make_float2(p10, p11);
            acc[nt][0] *= c0; acc[nt][1] *= c0;
            acc[nt][2] *= c1; acc[nt][3] *= c1;
        }
        __syncwarp();

        // ---- acc += P @ V ----
#pragma unroll
        for (int kb = 0; kb < 8; kb++) {
            unsigned a[4];
            a[0] = __float_as_uint(Pw[grp * PS_STR + kb * 8 + tig]);
            a[1] = __float_as_uint(Pw[(grp + 8) * PS_STR + kb * 8 + tig]);
            a[2] = __float_as_uint(Pw[grp * PS_STR + kb * 8 + tig + 4]);
            a[3] = __float_as_uint(Pw[(grp + 8) * PS_STR + kb * 8 + tig + 4]);
#pragma unroll
            for (int nt = 0; nt < 8; nt++) {
                unsigned b0 = __float_as_uint(Vc[(kb * 8 + tig) * VHS_STR + nt * 8 + grp]);
                unsigned b1 = __float_as_uint(Vc[(kb * 8 + tig + 4) * VHS_STR + nt * 8 + grp]);
                mma_tf32(acc[nt], a, b0, b1);
            }
        }

        __syncthreads();
        if (tid == 0 && t + 3 < AT_NT) {
            mbar_expect(mb0 + 8 * s, 17408 + 18432);
            bulk_g2s(smaddr(Ks + s * KTILE_F), ksrc + (size_t)(t + 3) * KTILE_F, 17408, mb0 + 8 * s);
            bulk_g2s(smaddr(Vs + s * VTILE_F), vsrc + (size_t)(t + 3) * VTILE_F, 18432, mb0 + 8 * s);
        }
    }

    // ---- finalize: write blocked layout for gemm2 ----
    l0 += __shfl_xor_sync(0xffffffff, l0, 1);
    l0 += __shfl_xor_sync(0xffffffff, l0, 2);
    l1 += __shfl_xor_sync(0xffffffff, l1, 1);
    l1 += __shfl_xor_sync(0xffffffff, l1, 2);
    float inv0 = 1.f / l0, inv1 = 1.f / l1;

    int r0 = qb * 256 + w * 16 + grp;
    int r1 = r0 + 8;
#pragma unroll
    for (int nt = 0; nt < 8; nt++) {
        int col = h * HDIM + nt * 8 + 2 * tig;
        int kt = col >> 4, c = col & 15;
        size_t o0 = ((size_t)(r0 >> 7) * 64 + kt) * BLKW + (r0 & 127) * 20 + c;
        size_t o1 = ((size_t)(r1 >> 7) * 64 + kt) * BLKW + (r1 & 127) * 20 + c;
        *(uint2*)(g_attn_blk + o0) = make_uint2(f2tf32(acc[nt][0] * inv0), f2tf32(acc[nt][1] * inv0));
        *(uint2*)(g_attn_blk + o1) = make_uint2(f2tf32(acc[nt][2] * inv1), f2tf32(acc[nt][3] * inv1));
    }
}

// ---------------------------------------------------------------------------
extern "C" void kernel_launch(void* const* d_in, const int* in_sizes, int n_in,
                              void* d_out, int out_size)
{
    const float* utter = (const float*)d_in[0];
    const float* rctx  = (const float*)d_in[1];
    const float* mem   = (const float*)d_in[2];
    const float* lck   = (const float*)d_in[3];
    const float* lcv   = (const float*)d_in[4];
    const float* Wq    = (const float*)d_in[5];
    const float* bq    = (const float*)d_in[6];
    const float* Wkv   = (const float*)d_in[7];
    const float* bkv   = (const float*)d_in[8];
    const float* Wo    = (const float*)d_in[9];
    const float* bo    = (const float*)d_in[10];

    float* out = (float*)d_out;                       // [2304, 1024]
    float* key = out + (size_t)QLEN * D_DIM;          // [3840, 1024]
    float* val = key + (size_t)KVLEN * D_DIM;         // [3840, 1024]

    static bool attr_done = false;
    if (!attr_done) {
        cudaFuncSetAttribute(attn_mma, cudaFuncAttributeMaxDynamicSharedMemorySize, ATT_SMEM);
        cudaFuncSetAttribute(gemm_blk<0>, cudaFuncAttributeMaxDynamicSharedMemorySize, GEMM_SMEM);
        cudaFuncSetAttribute(gemm_blk<1>, cudaFuncAttributeMaxDynamicSharedMemorySize, GEMM_SMEM);
        cudaFuncSetAttribute(gemm_blk<2>, cudaFuncAttributeMaxDynamicSharedMemorySize, GEMM_SMEM);
        attr_done = true;
    }

    unsigned *wq_b, *wkv_b, *wo_b;
    cudaGetSymbolAddress((void**)&wq_b,  g_Wq_blk);
    cudaGetSymbolAddress((void**)&wkv_b, g_Wkv_blk);
    cudaGetSymbolAddress((void**)&wo_b,  g_Wo_blk);

    // 0) prepass conversions
    conv_w_blk<<<256, 256>>>(Wq,  wq_b,  D_DIM * D_DIM / 4);
    conv_w_blk<<<512, 256>>>(Wkv, wkv_b, 2 * D_DIM * D_DIM / 4);
    conv_w_blk<<<256, 256>>>(Wo,  wo_b,  D_DIM * D_DIM / 4);
    conv_kvin_blk<<<512, 256>>>(utter, rctx, mem);
    conv_lc<<<256, 256>>>(lck, lcv);

    // 1) query projection -> g_query_t (pre-scaled tf32)
    gemm_blk<0><<<dim3(D_DIM / 128, QLEN / 128), 256, GEMM_SMEM>>>(bq, nullptr, nullptr);

    // 2) kv projection -> key/value (fp32) + head-major padded copies
    gemm_blk<1><<<dim3(2 * D_DIM / 128, KVIN / 128), 256, GEMM_SMEM>>>(bkv, key, val);

    // 3) left-context splice into d_out (contiguous)
    cudaMemcpyAsync(key + (size_t)MR * D_DIM, lck,
                    (size_t)L_LEN * D_DIM * sizeof(float),
                    cudaMemcpyDeviceToDevice, 0);
    cudaMemcpyAsync(val + (size_t)MR * D_DIM, lcv,
                    (size_t)L_LEN * D_DIM * sizeof(float),
                    cudaMemcpyDeviceToDevice, 0);

    // 4) attention -> g_attn_blk (blocked tf32)
    attn_mma<<<dim3(NHEAD, QLEN / 256), 512, ATT_SMEM>>>(0);

    // 5) output projection
    gemm_blk<2><<<dim3(D_DIM / 128, QLEN / 128), 256, GEMM_SMEM>>>(bo, out, nullptr);
}